// round 15
// baseline (speedup 1.0000x reference)
#include <cuda_runtime.h>
#include <cuda_bf16.h>
#include <cstdint>
#include <math.h>

#define NB 2
#define NN 4096
#define NC 256
#define NH 8
#define NK 32
#define NM (NB*NN)   // 8192

typedef __nv_bfloat16 bf16;

// ---------------- scratch (device globals; no allocation) ----------------
__device__ float g_qs [NM*NC];
__device__ float g_ks [NM*NC];
__device__ float g_v  [NM*NC];
__device__ float g_qd [NM*NC];
__device__ float g_kd [NM*NC];
__device__ int   g_idx[NM*NK];
__device__ float g_y2 [NM*NC];

// bf16 split activations (A operands, row layout [hi | lo | hi], K' = 3K)
__device__ bf16 g_xAnb[(size_t)NM*768];    // K=256 -> 768
__device__ bf16 g_xBb [(size_t)NM*768];
__device__ bf16 g_f1b [(size_t)NM*2304];   // concat K=768 -> 2304
__device__ bf16 g_y1b [(size_t)NM*1536];   // K=512 -> 1536
// bf16 split weights (B operands, row layout [hi | hi | lo], [O][3K])
__device__ bf16 g_wAb[(size_t)512*768];    // wq|wqd rows
__device__ bf16 g_wBb[(size_t)768*768];    // wk|wv|wkd rows
__device__ bf16 g_w1b[(size_t)512*2304];
__device__ bf16 g_w2b[(size_t)256*1536];

__device__ __forceinline__ void bsplit(float v, bf16& h, bf16& l) {
  h = __float2bfloat16(v);
  l = __float2bfloat16(v - __bfloat162float(h));
}

// ---------------- weight prep: bf16 split, [O][3K] ----------------
__global__ void prep_weights(const float* wq, const float* wk, const float* wv,
                             const float* wqd, const float* wkd,
                             const float* w1, const float* w2) {
  int i = blockIdx.x * blockDim.x + threadIdx.x;
  const int S5 = 5 * NC * NC;          // 327680
  const int S1 = S5 + 3*NC*2*NC;       // 720896
  const int TOT = S1 + 2*NC*NC;        // 851968
  if (i >= TOT) return;
  bf16 h, l;
  if (i < S5) {
    int r = i / (NC*NC);
    int t = i - r*(NC*NC);
    const float* src = (r==0)?wq:(r==1)?wk:(r==2)?wv:(r==3)?wqd:wkd;
    int o = t / NC, k = t - o*NC;
    bsplit(src[t], h, l);
    bf16* dst; int row;
    if (r == 0)      { dst = g_wAb; row = o; }
    else if (r == 3) { dst = g_wAb; row = NC + o; }
    else if (r == 1) { dst = g_wBb; row = o; }
    else if (r == 2) { dst = g_wBb; row = NC + o; }
    else             { dst = g_wBb; row = 2*NC + o; }
    size_t base = (size_t)row * 768;
    dst[base + k] = h; dst[base + 256 + k] = h; dst[base + 512 + k] = l;
  } else if (i < S1) {
    int t = i - S5; int o = t / 768, k = t - o*768;   // w1 [512][768]
    bsplit(w1[t], h, l);
    size_t base = (size_t)o * 2304;
    g_w1b[base + k] = h; g_w1b[base + 768 + k] = h; g_w1b[base + 1536 + k] = l;
  } else {
    int t = i - S1; int o = t / 512, k = t - o*512;   // w2 [256][512]
    bsplit(w2[t], h, l);
    size_t base = (size_t)o * 1536;
    g_w2b[base + k] = h; g_w2b[base + 512 + k] = h; g_w2b[base + 1024 + k] = l;
  }
}

// ---------------- featB (B,C,N) -> xBb (B,N,3C) bf16 split ----------------
__global__ void transpose_feat(const float* f) {
  __shared__ float t[32][33];
  int b = blockIdx.z;
  int n0 = blockIdx.x*32, c0 = blockIdx.y*32;
  int tx = threadIdx.x, ty = threadIdx.y;
  #pragma unroll
  for (int i = ty; i < 32; i += 8)
    t[i][tx] = f[((size_t)b*NC + c0+i)*NN + n0 + tx];
  __syncthreads();
  #pragma unroll
  for (int i = ty; i < 32; i += 8) {
    bf16 h, l; bsplit(t[tx][i], h, l);
    size_t base = ((size_t)b*NN + n0+i)*768 + c0 + tx;
    g_xBb[base] = h; g_xBb[base + 256] = l; g_xBb[base + 512] = h;
  }
}

// ---------------- fused transpose + LayerNorm: featA -> xAnb + f1b ----------------
__global__ void ln_input(const float* fA, const float* w, const float* bia) {
  __shared__ float t[32][NC+1];
  int b = blockIdx.y;
  int n0 = blockIdx.x*32;
  int tx = threadIdx.x, ty = threadIdx.y;
  for (int c = ty; c < NC; c += 8)
    t[tx][c] = fA[((size_t)b*NC + c)*NN + n0 + tx];
  __syncthreads();
  int warp = ty, lane = tx;
  #pragma unroll
  for (int r = 0; r < 4; r++) {
    int nl = warp*4 + r;
    float s = 0.f, sq = 0.f;
    #pragma unroll
    for (int i = 0; i < 8; i++) { float v = t[nl][lane + 32*i]; s += v; sq += v*v; }
    #pragma unroll
    for (int off = 16; off; off >>= 1) {
      s  += __shfl_xor_sync(0xffffffffu, s, off);
      sq += __shfl_xor_sync(0xffffffffu, sq, off);
    }
    float mean = s * (1.f/NC);
    float var  = sq * (1.f/NC) - mean*mean;
    float rs   = rsqrtf(var + 1e-5f);
    size_t m = (size_t)b*NN + n0 + nl;
    size_t o7 = m*768, oF = m*2304;
    #pragma unroll
    for (int i = 0; i < 8; i++) {
      int c = lane + 32*i;
      float v = (t[nl][c] - mean) * rs * w[c] + bia[c];
      bf16 h, l; bsplit(v, h, l);
      g_xAnb[o7 + c] = h; g_xAnb[o7 + 256 + c] = l; g_xAnb[o7 + 512 + c] = h;
      g_f1b[oF + c] = h;  g_f1b[oF + 768 + c] = l;  g_f1b[oF + 1536 + c] = h;
    }
  }
}

// ---------------- KNN v4: 16 queries/block (512 thr), sorted-insert top-32 ----------------
__device__ __forceinline__ unsigned long long warp_sort32(unsigned long long key, int lane) {
  #pragma unroll
  for (int k = 2; k <= 32; k <<= 1) {
    #pragma unroll
    for (int j = k >> 1; j > 0; j >>= 1) {
      unsigned long long o = __shfl_xor_sync(0xffffffffu, key, j);
      bool up = ((lane & k) == 0);
      bool takeMin = (((lane & j) == 0) == up);
      unsigned long long mn = (key < o) ? key : o;
      unsigned long long mx = (key < o) ? o : key;
      key = takeMin ? mn : mx;
    }
  }
  return key;
}

__global__ __launch_bounds__(512) void knn_kernel(const float* xyzA, const float* xyzB) {
  __shared__ float sx[NN], sy[NN], sz[NN];
  int b = blockIdx.x >> 8;             // 256 blocks per batch (16 queries each)
  int tid = threadIdx.x;
  int lane = tid & 31, warp = tid >> 5;
  int q = blockIdx.x * 16 + warp;

  const float* Bp = xyzB + (size_t)b*NN*3;
  for (int i = tid; i < NN*3; i += 512) {
    float v = Bp[i];
    int p = i / 3, c = i - p*3;
    if (c == 0) sx[p] = v; else if (c == 1) sy[p] = v; else sz[p] = v;
  }
  __syncthreads();

  const float* Ap = xyzA + (size_t)q*3;
  float ax = Ap[0], ay = Ap[1], az = Ap[2];
  float sA = ax*ax + ay*ay + az*az;

  auto mkkey = [&](int j) -> unsigned long long {
    float bx = sx[j], by = sy[j], bz = sz[j];
    float d2 = sA + (bx*bx + by*by + bz*bz) - 2.f*(ax*bx + ay*by + az*bz);
    unsigned u = __float_as_uint(d2);
    u = (u & 0x80000000u) ? ~u : (u | 0x80000000u);
    return ((unsigned long long)u << 32) | (unsigned)j;
  };

  unsigned long long topk = warp_sort32(mkkey(lane), lane);
  unsigned long long thr = __shfl_sync(0xffffffffu, topk, 31);

  for (int it = 1; it < NN/32; it++) {
    unsigned long long ck = mkkey(it*32 + lane);
    unsigned ball = __ballot_sync(0xffffffffu, ck < thr);
    while (ball) {
      int src = __ffs(ball) - 1;
      ball &= ball - 1;
      unsigned long long cand = __shfl_sync(0xffffffffu, ck, src);
      if (cand >= thr) continue;
      unsigned long long prev = __shfl_up_sync(0xffffffffu, topk, 1);
      bool shift = (topk > cand);
      unsigned long long nv = (lane > 0 && prev > cand) ? prev : cand;
      topk = shift ? nv : topk;
      thr = __shfl_sync(0xffffffffu, topk, 31);
    }
  }
  g_idx[(size_t)q*NK + lane] = (int)(unsigned)(topk & 0xffffffffull);
}

// ---------------- dual-path attention (gather + softmax + ctx + LN) ----------------
__global__ __launch_bounds__(256) void attn_kernel(const float* lsw, const float* lsb,
                                                   const float* ldw, const float* ldb) {
  int q = blockIdx.x;
  int b = q >> 12;
  int tid = threadIdx.x, h = tid >> 5, lane = tid & 31;
  __shared__ int sidx[NK];
  __shared__ float sS[NH][NK];
  __shared__ float sD[NH][NK];
  __shared__ float4 rbuf[NH];
  if (tid < NK) sidx[tid] = g_idx[(size_t)q*NK + tid];
  __syncthreads();
  float qs = g_qs[(size_t)q*NC + tid];
  float qd = g_qd[(size_t)q*NC + tid];
  size_t bb = (size_t)b*NN*NC;
  #pragma unroll
  for (int k0 = 0; k0 < NK; k0 += 4) {
    float a[4], c[4];
    #pragma unroll
    for (int u = 0; u < 4; u++) {
      size_t base = bb + (size_t)sidx[k0+u]*NC + tid;
      a[u] = g_ks[base];
      c[u] = g_kd[base];
    }
    #pragma unroll
    for (int u = 0; u < 4; u++) {
      float ps = qs * a[u];
      float df = qd - c[u];
      float pd = df * df;
      #pragma unroll
      for (int off = 16; off; off >>= 1) {
        ps += __shfl_down_sync(0xffffffffu, ps, off);
        pd += __shfl_down_sync(0xffffffffu, pd, off);
      }
      if (lane == 0) {
        sS[h][k0+u] = ps * 0.17677669529663687f;
        sD[h][k0+u] = sqrtf(pd);
      }
    }
  }
  __syncwarp();
  {
    float sv = sS[h][lane];
    float mx = sv;
    #pragma unroll
    for (int off = 16; off; off >>= 1) mx = fmaxf(mx, __shfl_xor_sync(0xffffffffu, mx, off));
    float e = expf(sv - mx);
    float s = e;
    #pragma unroll
    for (int off = 16; off; off >>= 1) s += __shfl_xor_sync(0xffffffffu, s, off);
    sS[h][lane] = e / s;

    float dv = sD[h][lane];
    float mx2 = dv;
    #pragma unroll
    for (int off = 16; off; off >>= 1) mx2 = fmaxf(mx2, __shfl_xor_sync(0xffffffffu, mx2, off));
    float e2 = expf(dv - mx2);
    float s2 = e2;
    #pragma unroll
    for (int off = 16; off; off >>= 1) s2 += __shfl_xor_sync(0xffffffffu, s2, off);
    sD[h][lane] = e2 / s2;
  }
  __syncwarp();
  float accs = 0.f, accd = 0.f;
  #pragma unroll
  for (int k0 = 0; k0 < NK; k0 += 4) {
    float vv[4];
    #pragma unroll
    for (int u = 0; u < 4; u++) vv[u] = g_v[bb + (size_t)sidx[k0+u]*NC + tid];
    #pragma unroll
    for (int u = 0; u < 4; u++) { accs += sS[h][k0+u]*vv[u]; accd += sD[h][k0+u]*vv[u]; }
  }
  float4 red = make_float4(accs, accs*accs, accd, accd*accd);
  #pragma unroll
  for (int off = 16; off; off >>= 1) {
    red.x += __shfl_xor_sync(0xffffffffu, red.x, off);
    red.y += __shfl_xor_sync(0xffffffffu, red.y, off);
    red.z += __shfl_xor_sync(0xffffffffu, red.z, off);
    red.w += __shfl_xor_sync(0xffffffffu, red.w, off);
  }
  if (lane == 0) rbuf[h] = red;
  __syncthreads();
  float4 tot = rbuf[0];
  #pragma unroll
  for (int w = 1; w < 8; w++) { float4 r = rbuf[w]; tot.x += r.x; tot.y += r.y; tot.z += r.z; tot.w += r.w; }
  float ms = tot.x * (1.f/NC), vs = tot.y * (1.f/NC) - ms*ms;
  float md = tot.z * (1.f/NC), vd = tot.w * (1.f/NC) - md*md;
  float ys = (accs - ms) * rsqrtf(vs + 1e-5f) * lsw[tid] + lsb[tid];
  float yd = (accd - md) * rsqrtf(vd + 1e-5f) * ldw[tid] + ldb[tid];
  size_t oF = (size_t)q*2304;
  bf16 hh, ll;
  bsplit(ys, hh, ll);   // ctx_s occupies concat cols [256,512)
  g_f1b[oF + 256 + tid] = hh; g_f1b[oF + 1024 + tid] = ll; g_f1b[oF + 1792 + tid] = hh;
  bsplit(yd, hh, ll);   // ctx_d occupies concat cols [512,768)
  g_f1b[oF + 512 + tid] = hh; g_f1b[oF + 1280 + tid] = ll; g_f1b[oF + 2048 + tid] = hh;
}

// ================= bf16 tensor-core GEMM via mma.sync + cp.async (sm_100 baseline ISA) =================
__device__ __forceinline__ uint32_t smem_u32(const void* p) {
  uint32_t a;
  asm("{ .reg .u64 t; cvta.to.shared.u64 t, %1; cvt.u32.u64 %0, t; }" : "=r"(a) : "l"(p));
  return a;
}
__device__ __forceinline__ void ldsm4(uint32_t* r, uint32_t addr) {
  asm volatile("ldmatrix.sync.aligned.m8n8.x4.shared.b16 {%0,%1,%2,%3}, [%4];"
    : "=r"(r[0]), "=r"(r[1]), "=r"(r[2]), "=r"(r[3]) : "r"(addr));
}
__device__ __forceinline__ void mma16816(float* d, const uint32_t* a, const uint32_t* b) {
  asm volatile("mma.sync.aligned.m16n8k16.row.col.f32.bf16.bf16.f32 "
    "{%0,%1,%2,%3}, {%4,%5,%6,%7}, {%8,%9}, {%0,%1,%2,%3};"
    : "+f"(d[0]), "+f"(d[1]), "+f"(d[2]), "+f"(d[3])
    : "r"(a[0]), "r"(a[1]), "r"(a[2]), "r"(a[3]), "r"(b[0]), "r"(b[1]));
}
__device__ __forceinline__ void cpasync16(uint32_t dst, const void* src) {
  asm volatile("cp.async.cg.shared.global [%0], [%1], 16;" :: "r"(dst), "l"(src) : "memory");
}

__device__ __forceinline__ const bf16* selAb(int s) {
  switch (s) { case 0: return g_xAnb; case 1: return g_xBb; case 2: return g_f1b; }
  return g_y1b;
}
__device__ __forceinline__ const bf16* selWb(int s) {
  switch (s) { case 0: return g_wAb; case 1: return g_wBb; case 2: return g_w1b; }
  return g_w2b;
}

#define KCH 64      // K-chunk width (bf16)
#define SROW 72     // smem row stride in bf16 (144 B) — conflict-free LDSM phases
#define STAGE_A (64*SROW)    // A: BM=64 rows
#define STAGE_B (128*SROW)   // B: BN=128 rows
#define HGEMM_SMEM ((2*STAGE_A + 2*STAGE_B)*2)   // 2 stages x (A+B) = 55296 B

extern __shared__ __align__(16) bf16 hg_dyn[];

// BM=64, BN=128 tile; 8 warps as 2M x 4N (32x32 warp tiles); 32 acc regs/thread
__global__ __launch_bounds__(256, 3) void hgemm(int Kp, int aSel, int wSel, int outSel,
                                                const float* e1, const float* e2, const float* e3) {
  const int tid = threadIdx.x;
  const int warp = tid >> 5, lane = tid & 31;
  const int wm = (warp & 1) * 32;    // warp M offset (2 warps in M)
  const int wn = (warp >> 1) * 32;   // warp N offset (4 warps in N)
  const int m0 = blockIdx.y * 64;
  const int n0 = blockIdx.x * 128;
  const bf16* Ab = selAb(aSel);
  const bf16* Wb = selWb(wSel);
  const uint32_t sA = smem_u32(hg_dyn);            // stages 0,1 of A
  const uint32_t sB = sA + 2*STAGE_A*2;            // stages 0,1 of B

  float acc[2][4][4];
  #pragma unroll
  for (int i = 0; i < 2; i++)
    #pragma unroll
    for (int j = 0; j < 4; j++)
      #pragma unroll
      for (int c = 0; c < 4; c++) acc[i][j][c] = 0.f;

  // cp.async: A chunk 64x64 = 512x16B (2/thread); B chunk 128x64 = 1024x16B (4/thread)
  const int gRow = tid >> 3;           // rows 0..31
  const int gSeg = (tid & 7) * 8;      // bf16 offset within chunk row

  auto cpload = [&](int buf, int ch) {
    #pragma unroll
    for (int i = 0; i < 2; i++) {
      int row = gRow + i*32;
      cpasync16(sA + (buf*STAGE_A + row*SROW + gSeg)*2,
                Ab + (size_t)(m0 + row)*Kp + ch*KCH + gSeg);
    }
    #pragma unroll
    for (int i = 0; i < 4; i++) {
      int row = gRow + i*32;
      cpasync16(sB + (buf*STAGE_B + row*SROW + gSeg)*2,
                Wb + (size_t)(n0 + row)*Kp + ch*KCH + gSeg);
    }
    asm volatile("cp.async.commit_group;" ::: "memory");
  };

  // ldmatrix address components
  const int aRowSel = lane & 15;            // m-row within 16
  const int aKSel   = (lane >> 4) * 8;      // k-offset 0/8
  const int bMtx    = lane >> 3;            // 0..3
  const int bRowSel = lane & 7;
  const int bNOff   = (bMtx >> 1) * 8;
  const int bKOff   = (bMtx & 1) * 8;

  const int nCh = Kp / KCH;
  cpload(0, 0);
  for (int ch = 0; ch < nCh; ch++) {
    if (ch + 1 < nCh) {
      cpload((ch + 1) & 1, ch + 1);
      asm volatile("cp.async.wait_group 1;" ::: "memory");
    } else {
      asm volatile("cp.async.wait_group 0;" ::: "memory");
    }
    __syncthreads();
    const uint32_t aOff = (uint32_t)((ch & 1) * STAGE_A) * 2;
    const uint32_t bOff = (uint32_t)((ch & 1) * STAGE_B) * 2;
    #pragma unroll
    for (int ks = 0; ks < KCH/16; ks++) {
      uint32_t af[2][4], bfr[4][2];
      #pragma unroll
      for (int mi = 0; mi < 2; mi++) {
        uint32_t addr = sA + aOff + ((wm + mi*16 + aRowSel)*SROW + ks*16 + aKSel)*2;
        ldsm4(af[mi], addr);
      }
      #pragma unroll
      for (int p = 0; p < 2; p++) {
        uint32_t r[4];
        uint32_t addr = sB + bOff + ((wn + p*16 + bNOff + bRowSel)*SROW + ks*16 + bKOff)*2;
        ldsm4(r, addr);
        bfr[2*p][0] = r[0]; bfr[2*p][1] = r[1];
        bfr[2*p+1][0] = r[2]; bfr[2*p+1][1] = r[3];
      }
      #pragma unroll
      for (int mi = 0; mi < 2; mi++)
        #pragma unroll
        for (int ni = 0; ni < 4; ni++)
          mma16816(acc[mi][ni], af[mi], bfr[ni]);
    }
    __syncthreads();   // buffer (ch&1) reusable for cp.async next iteration
  }

  // ---- epilogue ----
  const int t4 = lane & 3, qd = lane >> 2;
  const float BNS = rsqrtf(1.f + 1e-5f);
  #pragma unroll
  for (int mi = 0; mi < 2; mi++) {
    #pragma unroll
    for (int half = 0; half < 2; half++) {
      int m = m0 + wm + mi*16 + qd + half*8;
      #pragma unroll
      for (int ni = 0; ni < 4; ni++) {
        int n = n0 + wn + ni*8 + t4*2;
        float v0 = acc[mi][ni][half*2 + 0];
        float v1 = acc[mi][ni][half*2 + 1];
        if (outSel == 5) {               // fusion1: BN + ReLU -> bf16 split y1b
          float y0 = fmaxf(v0 * BNS * e1[n]   + e2[n],   0.f);
          float y1 = fmaxf(v1 * BNS * e1[n+1] + e2[n+1], 0.f);
          bf16 h0, l0, h1, l1; bsplit(y0, h0, l0); bsplit(y1, h1, l1);
          size_t base = (size_t)m*1536 + n;
          g_y1b[base]        = h0; g_y1b[base+1]      = h1;
          g_y1b[base + 512]  = l0; g_y1b[base+513]    = l1;
          g_y1b[base + 1024] = h0; g_y1b[base+1025]   = h1;
        } else if (outSel == 6) {        // fusion2: +bias -> fp32 y2
          float2 o2 = make_float2(v0 + e1[n], v1 + e1[n+1]);
          *(float2*)(g_y2 + (size_t)m*NC + n) = o2;
        } else {                         // projections: +bias -> fp32 segment
          float* dst; const float* bias;
          if (outSel == 10) { dst = (n < 256) ? g_qs : g_qd; bias = (n < 256) ? e1 : e2; }
          else { int sg = n >> 8; dst = (sg == 0) ? g_ks : (sg == 1) ? g_v : g_kd;
                 bias = (sg == 0) ? e1 : (sg == 1) ? e2 : e3; }
          int lc = n & 255;
          float2 o2 = make_float2(v0 + bias[lc], v1 + bias[lc+1]);
          *(float2*)(dst + (size_t)m*NC + lc) = o2;
        }
      }
    }
  }
}

// ---------------- final: out(b,c,n) = y2(b,n,c) + featA(b,c,n) ----------------
__global__ void out_addT(const float* fA, float* out) {
  __shared__ float t[32][33];
  int b = blockIdx.z;
  int n0 = blockIdx.x*32, c0 = blockIdx.y*32;
  int tx = threadIdx.x, ty = threadIdx.y;
  #pragma unroll
  for (int i = ty; i < 32; i += 8)
    t[i][tx] = g_y2[((size_t)b*NN + n0+i)*NC + c0 + tx];
  __syncthreads();
  #pragma unroll
  for (int i = ty; i < 32; i += 8) {
    size_t o = ((size_t)b*NC + c0+i)*NN + n0 + tx;
    out[o] = t[tx][i] + fA[o];
  }
}

// ---------------- launch ----------------
extern "C" void kernel_launch(void* const* d_in, const int* in_sizes, int n_in,
                              void* d_out, int out_size) {
  const float* xyzA   = (const float*)d_in[0];
  const float* xyzB   = (const float*)d_in[1];
  const float* featA  = (const float*)d_in[2];
  const float* featB  = (const float*)d_in[3];
  const float* ln_in_w = (const float*)d_in[4];
  const float* ln_in_b = (const float*)d_in[5];
  const float* wq  = (const float*)d_in[6];  const float* bq  = (const float*)d_in[7];
  const float* wk  = (const float*)d_in[8];  const float* bk  = (const float*)d_in[9];
  const float* wv  = (const float*)d_in[10]; const float* bv  = (const float*)d_in[11];
  const float* wqd = (const float*)d_in[12]; const float* bqd = (const float*)d_in[13];
  const float* wkd = (const float*)d_in[14]; const float* bkd = (const float*)d_in[15];
  const float* lsw = (const float*)d_in[16]; const float* lsb = (const float*)d_in[17];
  const float* ldw = (const float*)d_in[18]; const float* ldb = (const float*)d_in[19];
  const float* w1  = (const float*)d_in[20];
  const float* bng = (const float*)d_in[21]; const float* bnb = (const float*)d_in[22];
  const float* w2  = (const float*)d_in[23]; const float* b2  = (const float*)d_in[24];

  // side streams + fork/join events (created once; identical captured work per call)
  static cudaStream_t s1 = nullptr, s2 = nullptr, s3 = nullptr;
  static cudaEvent_t evFork = nullptr, evPrep = nullptr, evKnn = nullptr,
                     evP1 = nullptr, evP2 = nullptr;
  if (s1 == nullptr) {
    cudaStreamCreateWithFlags(&s1, cudaStreamNonBlocking);
    cudaStreamCreateWithFlags(&s2, cudaStreamNonBlocking);
    cudaStreamCreateWithFlags(&s3, cudaStreamNonBlocking);
    cudaEventCreateWithFlags(&evFork, cudaEventDisableTiming);
    cudaEventCreateWithFlags(&evPrep, cudaEventDisableTiming);
    cudaEventCreateWithFlags(&evKnn,  cudaEventDisableTiming);
    cudaEventCreateWithFlags(&evP1,   cudaEventDisableTiming);
    cudaEventCreateWithFlags(&evP2,   cudaEventDisableTiming);
  }

  cudaFuncSetAttribute(hgemm, cudaFuncAttributeMaxDynamicSharedMemorySize, HGEMM_SMEM);

  // ---- fork: 4 independent front-end branches ----
  cudaEventRecord(evFork, 0);
  cudaStreamWaitEvent(s1, evFork, 0);
  cudaStreamWaitEvent(s2, evFork, 0);
  cudaStreamWaitEvent(s3, evFork, 0);

  // s1: knn (ALU-bound, long) — overlaps everything up to attn
  knn_kernel<<<NM/16, 512, 0, s1>>>(xyzA, xyzB);
  cudaEventRecord(evKnn, s1);

  // main: weight prep (needed by all GEMMs)
  prep_weights<<<(851968 + 255)/256, 256>>>(wq, wk, wv, wqd, wkd, w1, w2);
  cudaEventRecord(evPrep, 0);

  // s2: ln_input -> proj1 (q_s|q_d)
  ln_input<<<dim3(128,2), dim3(32,8), 0, s2>>>(featA, ln_in_w, ln_in_b);
  cudaStreamWaitEvent(s2, evPrep, 0);
  hgemm<<<dim3(4,128), 256, HGEMM_SMEM, s2>>>(768, 0, 0, 10, bq, bqd, nullptr);
  cudaEventRecord(evP1, s2);

  // s3: transpose_feat -> proj2 (k_s|v|k_d)
  transpose_feat<<<dim3(128,8,2), dim3(32,8), 0, s3>>>(featB);
  cudaStreamWaitEvent(s3, evPrep, 0);
  hgemm<<<dim3(6,128), 256, HGEMM_SMEM, s3>>>(768, 1, 1, 11, bk, bv, bkd);
  cudaEventRecord(evP2, s3);

  // ---- join: attention needs knn indices + both projections ----
  cudaStreamWaitEvent(0, evKnn, 0);
  cudaStreamWaitEvent(0, evP1, 0);
  cudaStreamWaitEvent(0, evP2, 0);
  attn_kernel<<<NM, 256>>>(lsw, lsb, ldw, ldb);

  // fusion MLP: concat -> w1 (BN+ReLU) -> w2 (+b2)
  hgemm<<<dim3(4,128), 256, HGEMM_SMEM>>>(2304, 2, 2, 5, bng, bnb, nullptr);
  hgemm<<<dim3(2,128), 256, HGEMM_SMEM>>>(1536, 3, 3, 6, b2, nullptr, nullptr);

  out_addT<<<dim3(128,8,2), dim3(32,8)>>>(featA, (float*)d_out);
}

// round 16
// speedup vs baseline: 1.0249x; 1.0249x over previous
#include <cuda_runtime.h>
#include <cuda_bf16.h>
#include <cstdint>
#include <math.h>

#define NB 2
#define NN 4096
#define NC 256
#define NH 8
#define NK 32
#define NM (NB*NN)   // 8192

typedef __nv_bfloat16 bf16;

// ---------------- scratch (device globals; no allocation) ----------------
__device__ float g_qs [NM*NC];
__device__ float g_ks [NM*NC];
__device__ float g_v  [NM*NC];
__device__ float g_qd [NM*NC];
__device__ float g_kd [NM*NC];
__device__ int   g_idx[NM*NK];

// bf16 split activations (A operands, row layout [hi | lo | hi], K' = 3K)
__device__ bf16 g_xAnb[(size_t)NM*768];    // K=256 -> 768
__device__ bf16 g_xBb [(size_t)NM*768];
__device__ bf16 g_f1b [(size_t)NM*2304];   // concat K=768 -> 2304
__device__ bf16 g_y1b [(size_t)NM*1536];   // K=512 -> 1536
// bf16 split weights (B operands, row layout [hi | hi | lo], [O][3K])
__device__ bf16 g_wAb[(size_t)512*768];    // wq|wqd rows
__device__ bf16 g_wBb[(size_t)768*768];    // wk|wv|wkd rows
__device__ bf16 g_w1b[(size_t)512*2304];
__device__ bf16 g_w2b[(size_t)256*1536];

__device__ __forceinline__ void bsplit(float v, bf16& h, bf16& l) {
  h = __float2bfloat16(v);
  l = __float2bfloat16(v - __bfloat162float(h));
}

// ---------------- weight prep: bf16 split, [O][3K] ----------------
__global__ void prep_weights(const float* wq, const float* wk, const float* wv,
                             const float* wqd, const float* wkd,
                             const float* w1, const float* w2) {
  int i = blockIdx.x * blockDim.x + threadIdx.x;
  const int S5 = 5 * NC * NC;          // 327680
  const int S1 = S5 + 3*NC*2*NC;       // 720896
  const int TOT = S1 + 2*NC*NC;        // 851968
  if (i >= TOT) return;
  bf16 h, l;
  if (i < S5) {
    int r = i / (NC*NC);
    int t = i - r*(NC*NC);
    const float* src = (r==0)?wq:(r==1)?wk:(r==2)?wv:(r==3)?wqd:wkd;
    int o = t / NC, k = t - o*NC;
    bsplit(src[t], h, l);
    bf16* dst; int row;
    if (r == 0)      { dst = g_wAb; row = o; }
    else if (r == 3) { dst = g_wAb; row = NC + o; }
    else if (r == 1) { dst = g_wBb; row = o; }
    else if (r == 2) { dst = g_wBb; row = NC + o; }
    else             { dst = g_wBb; row = 2*NC + o; }
    size_t base = (size_t)row * 768;
    dst[base + k] = h; dst[base + 256 + k] = h; dst[base + 512 + k] = l;
  } else if (i < S1) {
    int t = i - S5; int o = t / 768, k = t - o*768;   // w1 [512][768]
    bsplit(w1[t], h, l);
    size_t base = (size_t)o * 2304;
    g_w1b[base + k] = h; g_w1b[base + 768 + k] = h; g_w1b[base + 1536 + k] = l;
  } else {
    int t = i - S1; int o = t / 512, k = t - o*512;   // w2 [256][512]
    bsplit(w2[t], h, l);
    size_t base = (size_t)o * 1536;
    g_w2b[base + k] = h; g_w2b[base + 512 + k] = h; g_w2b[base + 1024 + k] = l;
  }
}

// ---------------- featB (B,C,N) -> xBb (B,N,3C) bf16 split ----------------
__global__ void transpose_feat(const float* f) {
  __shared__ float t[32][33];
  int b = blockIdx.z;
  int n0 = blockIdx.x*32, c0 = blockIdx.y*32;
  int tx = threadIdx.x, ty = threadIdx.y;
  #pragma unroll
  for (int i = ty; i < 32; i += 8)
    t[i][tx] = f[((size_t)b*NC + c0+i)*NN + n0 + tx];
  __syncthreads();
  #pragma unroll
  for (int i = ty; i < 32; i += 8) {
    bf16 h, l; bsplit(t[tx][i], h, l);
    size_t base = ((size_t)b*NN + n0+i)*768 + c0 + tx;
    g_xBb[base] = h; g_xBb[base + 256] = l; g_xBb[base + 512] = h;
  }
}

// ---------------- fused transpose + LayerNorm: featA -> xAnb + f1b ----------------
__global__ void ln_input(const float* fA, const float* w, const float* bia) {
  __shared__ float t[32][NC+1];
  int b = blockIdx.y;
  int n0 = blockIdx.x*32;
  int tx = threadIdx.x, ty = threadIdx.y;
  for (int c = ty; c < NC; c += 8)
    t[tx][c] = fA[((size_t)b*NC + c)*NN + n0 + tx];
  __syncthreads();
  int warp = ty, lane = tx;
  #pragma unroll
  for (int r = 0; r < 4; r++) {
    int nl = warp*4 + r;
    float s = 0.f, sq = 0.f;
    #pragma unroll
    for (int i = 0; i < 8; i++) { float v = t[nl][lane + 32*i]; s += v; sq += v*v; }
    #pragma unroll
    for (int off = 16; off; off >>= 1) {
      s  += __shfl_xor_sync(0xffffffffu, s, off);
      sq += __shfl_xor_sync(0xffffffffu, sq, off);
    }
    float mean = s * (1.f/NC);
    float var  = sq * (1.f/NC) - mean*mean;
    float rs   = rsqrtf(var + 1e-5f);
    size_t m = (size_t)b*NN + n0 + nl;
    size_t o7 = m*768, oF = m*2304;
    #pragma unroll
    for (int i = 0; i < 8; i++) {
      int c = lane + 32*i;
      float v = (t[nl][c] - mean) * rs * w[c] + bia[c];
      bf16 h, l; bsplit(v, h, l);
      g_xAnb[o7 + c] = h; g_xAnb[o7 + 256 + c] = l; g_xAnb[o7 + 512 + c] = h;
      g_f1b[oF + c] = h;  g_f1b[oF + 768 + c] = l;  g_f1b[oF + 1536 + c] = h;
    }
  }
}

// ---------------- KNN v4: 16 queries/block (512 thr), sorted-insert top-32 ----------------
__device__ __forceinline__ unsigned long long warp_sort32(unsigned long long key, int lane) {
  #pragma unroll
  for (int k = 2; k <= 32; k <<= 1) {
    #pragma unroll
    for (int j = k >> 1; j > 0; j >>= 1) {
      unsigned long long o = __shfl_xor_sync(0xffffffffu, key, j);
      bool up = ((lane & k) == 0);
      bool takeMin = (((lane & j) == 0) == up);
      unsigned long long mn = (key < o) ? key : o;
      unsigned long long mx = (key < o) ? o : key;
      key = takeMin ? mn : mx;
    }
  }
  return key;
}

__global__ __launch_bounds__(512) void knn_kernel(const float* xyzA, const float* xyzB) {
  __shared__ float sx[NN], sy[NN], sz[NN];
  int b = blockIdx.x >> 8;             // 256 blocks per batch (16 queries each)
  int tid = threadIdx.x;
  int lane = tid & 31, warp = tid >> 5;
  int q = blockIdx.x * 16 + warp;

  const float* Bp = xyzB + (size_t)b*NN*3;
  for (int i = tid; i < NN*3; i += 512) {
    float v = Bp[i];
    int p = i / 3, c = i - p*3;
    if (c == 0) sx[p] = v; else if (c == 1) sy[p] = v; else sz[p] = v;
  }
  __syncthreads();

  const float* Ap = xyzA + (size_t)q*3;
  float ax = Ap[0], ay = Ap[1], az = Ap[2];
  float sA = ax*ax + ay*ay + az*az;

  auto mkkey = [&](int j) -> unsigned long long {
    float bx = sx[j], by = sy[j], bz = sz[j];
    float d2 = sA + (bx*bx + by*by + bz*bz) - 2.f*(ax*bx + ay*by + az*bz);
    unsigned u = __float_as_uint(d2);
    u = (u & 0x80000000u) ? ~u : (u | 0x80000000u);
    return ((unsigned long long)u << 32) | (unsigned)j;
  };

  unsigned long long topk = warp_sort32(mkkey(lane), lane);
  unsigned long long thr = __shfl_sync(0xffffffffu, topk, 31);

  for (int it = 1; it < NN/32; it++) {
    unsigned long long ck = mkkey(it*32 + lane);
    unsigned ball = __ballot_sync(0xffffffffu, ck < thr);
    while (ball) {
      int src = __ffs(ball) - 1;
      ball &= ball - 1;
      unsigned long long cand = __shfl_sync(0xffffffffu, ck, src);
      if (cand >= thr) continue;
      unsigned long long prev = __shfl_up_sync(0xffffffffu, topk, 1);
      bool shift = (topk > cand);
      unsigned long long nv = (lane > 0 && prev > cand) ? prev : cand;
      topk = shift ? nv : topk;
      thr = __shfl_sync(0xffffffffu, topk, 31);
    }
  }
  g_idx[(size_t)q*NK + lane] = (int)(unsigned)(topk & 0xffffffffull);
}

// ---------------- dual-path attention (gather + softmax + ctx + LN) ----------------
__global__ __launch_bounds__(256) void attn_kernel(const float* lsw, const float* lsb,
                                                   const float* ldw, const float* ldb) {
  int q = blockIdx.x;
  int b = q >> 12;
  int tid = threadIdx.x, h = tid >> 5, lane = tid & 31;
  __shared__ int sidx[NK];
  __shared__ float sS[NH][NK];
  __shared__ float sD[NH][NK];
  __shared__ float4 rbuf[NH];
  if (tid < NK) sidx[tid] = g_idx[(size_t)q*NK + tid];
  __syncthreads();
  float qs = g_qs[(size_t)q*NC + tid];
  float qd = g_qd[(size_t)q*NC + tid];
  size_t bb = (size_t)b*NN*NC;
  #pragma unroll
  for (int k0 = 0; k0 < NK; k0 += 4) {
    float a[4], c[4];
    #pragma unroll
    for (int u = 0; u < 4; u++) {
      size_t base = bb + (size_t)sidx[k0+u]*NC + tid;
      a[u] = g_ks[base];
      c[u] = g_kd[base];
    }
    #pragma unroll
    for (int u = 0; u < 4; u++) {
      float ps = qs * a[u];
      float df = qd - c[u];
      float pd = df * df;
      #pragma unroll
      for (int off = 16; off; off >>= 1) {
        ps += __shfl_down_sync(0xffffffffu, ps, off);
        pd += __shfl_down_sync(0xffffffffu, pd, off);
      }
      if (lane == 0) {
        sS[h][k0+u] = ps * 0.17677669529663687f;
        sD[h][k0+u] = sqrtf(pd);
      }
    }
  }
  __syncwarp();
  {
    float sv = sS[h][lane];
    float mx = sv;
    #pragma unroll
    for (int off = 16; off; off >>= 1) mx = fmaxf(mx, __shfl_xor_sync(0xffffffffu, mx, off));
    float e = expf(sv - mx);
    float s = e;
    #pragma unroll
    for (int off = 16; off; off >>= 1) s += __shfl_xor_sync(0xffffffffu, s, off);
    sS[h][lane] = e / s;

    float dv = sD[h][lane];
    float mx2 = dv;
    #pragma unroll
    for (int off = 16; off; off >>= 1) mx2 = fmaxf(mx2, __shfl_xor_sync(0xffffffffu, mx2, off));
    float e2 = expf(dv - mx2);
    float s2 = e2;
    #pragma unroll
    for (int off = 16; off; off >>= 1) s2 += __shfl_xor_sync(0xffffffffu, s2, off);
    sD[h][lane] = e2 / s2;
  }
  __syncwarp();
  float accs = 0.f, accd = 0.f;
  #pragma unroll
  for (int k0 = 0; k0 < NK; k0 += 4) {
    float vv[4];
    #pragma unroll
    for (int u = 0; u < 4; u++) vv[u] = g_v[bb + (size_t)sidx[k0+u]*NC + tid];
    #pragma unroll
    for (int u = 0; u < 4; u++) { accs += sS[h][k0+u]*vv[u]; accd += sD[h][k0+u]*vv[u]; }
  }
  float4 red = make_float4(accs, accs*accs, accd, accd*accd);
  #pragma unroll
  for (int off = 16; off; off >>= 1) {
    red.x += __shfl_xor_sync(0xffffffffu, red.x, off);
    red.y += __shfl_xor_sync(0xffffffffu, red.y, off);
    red.z += __shfl_xor_sync(0xffffffffu, red.z, off);
    red.w += __shfl_xor_sync(0xffffffffu, red.w, off);
  }
  if (lane == 0) rbuf[h] = red;
  __syncthreads();
  float4 tot = rbuf[0];
  #pragma unroll
  for (int w = 1; w < 8; w++) { float4 r = rbuf[w]; tot.x += r.x; tot.y += r.y; tot.z += r.z; tot.w += r.w; }
  float ms = tot.x * (1.f/NC), vs = tot.y * (1.f/NC) - ms*ms;
  float md = tot.z * (1.f/NC), vd = tot.w * (1.f/NC) - md*md;
  float ys = (accs - ms) * rsqrtf(vs + 1e-5f) * lsw[tid] + lsb[tid];
  float yd = (accd - md) * rsqrtf(vd + 1e-5f) * ldw[tid] + ldb[tid];
  size_t oF = (size_t)q*2304;
  bf16 hh, ll;
  bsplit(ys, hh, ll);   // ctx_s occupies concat cols [256,512)
  g_f1b[oF + 256 + tid] = hh; g_f1b[oF + 1024 + tid] = ll; g_f1b[oF + 1792 + tid] = hh;
  bsplit(yd, hh, ll);   // ctx_d occupies concat cols [512,768)
  g_f1b[oF + 512 + tid] = hh; g_f1b[oF + 1280 + tid] = ll; g_f1b[oF + 2048 + tid] = hh;
}

// ================= bf16 tensor-core GEMM via mma.sync + cp.async (sm_100 baseline ISA) =================
__device__ __forceinline__ uint32_t smem_u32(const void* p) {
  uint32_t a;
  asm("{ .reg .u64 t; cvta.to.shared.u64 t, %1; cvt.u32.u64 %0, t; }" : "=r"(a) : "l"(p));
  return a;
}
__device__ __forceinline__ void ldsm4(uint32_t* r, uint32_t addr) {
  asm volatile("ldmatrix.sync.aligned.m8n8.x4.shared.b16 {%0,%1,%2,%3}, [%4];"
    : "=r"(r[0]), "=r"(r[1]), "=r"(r[2]), "=r"(r[3]) : "r"(addr));
}
__device__ __forceinline__ void mma16816(float* d, const uint32_t* a, const uint32_t* b) {
  asm volatile("mma.sync.aligned.m16n8k16.row.col.f32.bf16.bf16.f32 "
    "{%0,%1,%2,%3}, {%4,%5,%6,%7}, {%8,%9}, {%0,%1,%2,%3};"
    : "+f"(d[0]), "+f"(d[1]), "+f"(d[2]), "+f"(d[3])
    : "r"(a[0]), "r"(a[1]), "r"(a[2]), "r"(a[3]), "r"(b[0]), "r"(b[1]));
}
__device__ __forceinline__ void cpasync16(uint32_t dst, const void* src) {
  asm volatile("cp.async.cg.shared.global [%0], [%1], 16;" :: "r"(dst), "l"(src) : "memory");
}

__device__ __forceinline__ const bf16* selAb(int s) {
  switch (s) { case 0: return g_xAnb; case 1: return g_xBb; case 2: return g_f1b; }
  return g_y1b;
}
__device__ __forceinline__ const bf16* selWb(int s) {
  switch (s) { case 0: return g_wAb; case 1: return g_wBb; case 2: return g_w1b; }
  return g_w2b;
}

#define KCH 64      // K-chunk width (bf16)
#define SROW 72     // smem row stride in bf16 (144 B) — conflict-free LDSM phases
#define STAGE (128*SROW)
#define HGEMM_SMEM (4*STAGE*2)   // 2 stages x (A+B) x 128xSROW bf16 = 73728 B

extern __shared__ __align__(16) bf16 hg_dyn[];

__global__ __launch_bounds__(256, 2) void hgemm(int Kp, int aSel, int wSel, int outSel,
                                                const float* e1, const float* e2, const float* e3,
                                                const float* fA, float* outp) {
  const int tid = threadIdx.x;
  const int warp = tid >> 5, lane = tid & 31;
  const int wm = (warp & 1) * 64;    // warp M offset (2 warps in M)
  const int wn = (warp >> 1) * 32;   // warp N offset (4 warps in N)
  const int m0 = blockIdx.y * 128;
  const int n0 = blockIdx.x * 128;
  const bf16* Ab = selAb(aSel);
  const bf16* Wb = selWb(wSel);
  const uint32_t sA = smem_u32(hg_dyn);            // stages 0,1 of A
  const uint32_t sB = sA + 2*STAGE*2;              // stages 0,1 of B

  float acc[4][4][4];
  #pragma unroll
  for (int i = 0; i < 4; i++)
    #pragma unroll
    for (int j = 0; j < 4; j++)
      #pragma unroll
      for (int c = 0; c < 4; c++) acc[i][j][c] = 0.f;

  // cp.async load: chunk = 128 rows x 64 bf16 = 1024 x 16B per operand; 4/thread
  const int gRow = tid >> 3;           // rows 0..31 (+32,+64,+96)
  const int gSeg = (tid & 7) * 8;      // bf16 offset within chunk row

  auto cpload = [&](int buf, int ch) {
    #pragma unroll
    for (int i = 0; i < 4; i++) {
      int row = gRow + i*32;
      uint32_t soff = (buf*STAGE + row*SROW + gSeg) * 2;
      cpasync16(sA + soff, Ab + (size_t)(m0 + row)*Kp + ch*KCH + gSeg);
      cpasync16(sB + soff, Wb + (size_t)(n0 + row)*Kp + ch*KCH + gSeg);
    }
    asm volatile("cp.async.commit_group;" ::: "memory");
  };

  // ldmatrix address components
  const int aRowSel = lane & 15;            // m-row within 16
  const int aKSel   = (lane >> 4) * 8;      // k-offset 0/8
  const int bMtx    = lane >> 3;            // 0..3
  const int bRowSel = lane & 7;
  const int bNOff   = (bMtx >> 1) * 8;
  const int bKOff   = (bMtx & 1) * 8;

  const int nCh = Kp / KCH;
  cpload(0, 0);
  for (int ch = 0; ch < nCh; ch++) {
    if (ch + 1 < nCh) {
      cpload((ch + 1) & 1, ch + 1);
      asm volatile("cp.async.wait_group 1;" ::: "memory");
    } else {
      asm volatile("cp.async.wait_group 0;" ::: "memory");
    }
    __syncthreads();
    const uint32_t bufOff = (uint32_t)((ch & 1) * STAGE) * 2;
    #pragma unroll
    for (int ks = 0; ks < KCH/16; ks++) {
      uint32_t af[4][4], bfr[4][2];
      #pragma unroll
      for (int mi = 0; mi < 4; mi++) {
        uint32_t addr = sA + bufOff + ((wm + mi*16 + aRowSel)*SROW + ks*16 + aKSel)*2;
        ldsm4(af[mi], addr);
      }
      #pragma unroll
      for (int p = 0; p < 2; p++) {
        uint32_t r[4];
        uint32_t addr = sB + bufOff + ((wn + p*16 + bNOff + bRowSel)*SROW + ks*16 + bKOff)*2;
        ldsm4(r, addr);
        bfr[2*p][0] = r[0]; bfr[2*p][1] = r[1];
        bfr[2*p+1][0] = r[2]; bfr[2*p+1][1] = r[3];
      }
      #pragma unroll
      for (int mi = 0; mi < 4; mi++)
        #pragma unroll
        for (int ni = 0; ni < 4; ni++)
          mma16816(acc[mi][ni], af[mi], bfr[ni]);
    }
    __syncthreads();   // buffer (ch&1) reusable for cp.async next iteration
  }

  // ---- epilogue ----
  const int t4 = lane & 3, qd = lane >> 2;
  const float BNS = rsqrtf(1.f + 1e-5f);
  #pragma unroll
  for (int mi = 0; mi < 4; mi++) {
    #pragma unroll
    for (int half = 0; half < 2; half++) {
      int m = m0 + wm + mi*16 + qd + half*8;
      #pragma unroll
      for (int ni = 0; ni < 4; ni++) {
        int n = n0 + wn + ni*8 + t4*2;
        float v0 = acc[mi][ni][half*2 + 0];
        float v1 = acc[mi][ni][half*2 + 1];
        if (outSel == 5) {               // fusion1: BN + ReLU -> bf16 split y1b
          float y0 = fmaxf(v0 * BNS * e1[n]   + e2[n],   0.f);
          float y1 = fmaxf(v1 * BNS * e1[n+1] + e2[n+1], 0.f);
          bf16 h0, l0, h1, l1; bsplit(y0, h0, l0); bsplit(y1, h1, l1);
          size_t base = (size_t)m*1536 + n;
          g_y1b[base]        = h0; g_y1b[base+1]      = h1;
          g_y1b[base + 512]  = l0; g_y1b[base+513]    = l1;
          g_y1b[base + 1024] = h0; g_y1b[base+1025]   = h1;
        } else if (outSel == 6) {        // fusion2: +bias + residual -> transposed out
          int bb2 = m >> 12, mt = m & 4095;
          size_t o0 = ((size_t)bb2*NC + n)*NN + mt;
          size_t o1 = o0 + NN;
          outp[o0] = v0 + e1[n]   + fA[o0];
          outp[o1] = v1 + e1[n+1] + fA[o1];
        } else {                         // projections: +bias -> fp32 segment
          float* dst; const float* bias;
          if (outSel == 10) { dst = (n < 256) ? g_qs : g_qd; bias = (n < 256) ? e1 : e2; }
          else { int sg = n >> 8; dst = (sg == 0) ? g_ks : (sg == 1) ? g_v : g_kd;
                 bias = (sg == 0) ? e1 : (sg == 1) ? e2 : e3; }
          int lc = n & 255;
          float2 o2 = make_float2(v0 + bias[lc], v1 + bias[lc+1]);
          *(float2*)(dst + (size_t)m*NC + lc) = o2;
        }
      }
    }
  }
}

// ---------------- launch ----------------
extern "C" void kernel_launch(void* const* d_in, const int* in_sizes, int n_in,
                              void* d_out, int out_size) {
  const float* xyzA   = (const float*)d_in[0];
  const float* xyzB   = (const float*)d_in[1];
  const float* featA  = (const float*)d_in[2];
  const float* featB  = (const float*)d_in[3];
  const float* ln_in_w = (const float*)d_in[4];
  const float* ln_in_b = (const float*)d_in[5];
  const float* wq  = (const float*)d_in[6];  const float* bq  = (const float*)d_in[7];
  const float* wk  = (const float*)d_in[8];  const float* bk  = (const float*)d_in[9];
  const float* wv  = (const float*)d_in[10]; const float* bv  = (const float*)d_in[11];
  const float* wqd = (const float*)d_in[12]; const float* bqd = (const float*)d_in[13];
  const float* wkd = (const float*)d_in[14]; const float* bkd = (const float*)d_in[15];
  const float* lsw = (const float*)d_in[16]; const float* lsb = (const float*)d_in[17];
  const float* ldw = (const float*)d_in[18]; const float* ldb = (const float*)d_in[19];
  const float* w1  = (const float*)d_in[20];
  const float* bng = (const float*)d_in[21]; const float* bnb = (const float*)d_in[22];
  const float* w2  = (const float*)d_in[23]; const float* b2  = (const float*)d_in[24];

  // side streams + fork/join events (created once; identical captured work per call)
  static cudaStream_t s1 = nullptr, s2 = nullptr, s3 = nullptr;
  static cudaEvent_t evFork = nullptr, evPrep = nullptr, evKnn = nullptr,
                     evP1 = nullptr, evP2 = nullptr;
  if (s1 == nullptr) {
    cudaStreamCreateWithFlags(&s1, cudaStreamNonBlocking);
    cudaStreamCreateWithFlags(&s2, cudaStreamNonBlocking);
    cudaStreamCreateWithFlags(&s3, cudaStreamNonBlocking);
    cudaEventCreateWithFlags(&evFork, cudaEventDisableTiming);
    cudaEventCreateWithFlags(&evPrep, cudaEventDisableTiming);
    cudaEventCreateWithFlags(&evKnn,  cudaEventDisableTiming);
    cudaEventCreateWithFlags(&evP1,   cudaEventDisableTiming);
    cudaEventCreateWithFlags(&evP2,   cudaEventDisableTiming);
  }

  cudaFuncSetAttribute(hgemm, cudaFuncAttributeMaxDynamicSharedMemorySize, HGEMM_SMEM);

  // ---- fork: 4 independent front-end branches ----
  cudaEventRecord(evFork, 0);
  cudaStreamWaitEvent(s1, evFork, 0);
  cudaStreamWaitEvent(s2, evFork, 0);
  cudaStreamWaitEvent(s3, evFork, 0);

  // s1: knn (ALU-bound, long) — overlaps everything up to attn
  knn_kernel<<<NM/16, 512, 0, s1>>>(xyzA, xyzB);
  cudaEventRecord(evKnn, s1);

  // main: weight prep (needed by all GEMMs)
  prep_weights<<<(851968 + 255)/256, 256>>>(wq, wk, wv, wqd, wkd, w1, w2);
  cudaEventRecord(evPrep, 0);

  // s2: ln_input -> proj1 (q_s|q_d)
  ln_input<<<dim3(128,2), dim3(32,8), 0, s2>>>(featA, ln_in_w, ln_in_b);
  cudaStreamWaitEvent(s2, evPrep, 0);
  hgemm<<<dim3(4,64), 256, HGEMM_SMEM, s2>>>(768, 0, 0, 10, bq, bqd, nullptr, nullptr, nullptr);
  cudaEventRecord(evP1, s2);

  // s3: transpose_feat -> proj2 (k_s|v|k_d)
  transpose_feat<<<dim3(128,8,2), dim3(32,8), 0, s3>>>(featB);
  cudaStreamWaitEvent(s3, evPrep, 0);
  hgemm<<<dim3(6,64), 256, HGEMM_SMEM, s3>>>(768, 1, 1, 11, bk, bv, bkd, nullptr, nullptr);
  cudaEventRecord(evP2, s3);

  // ---- join: attention needs knn indices + both projections ----
  cudaStreamWaitEvent(0, evKnn, 0);
  cudaStreamWaitEvent(0, evP1, 0);
  cudaStreamWaitEvent(0, evP2, 0);
  attn_kernel<<<NM, 256>>>(lsw, lsb, ldw, ldb);

  // fusion MLP: concat -> w1 (BN+ReLU) -> w2 (+b2 + residual, transposed store)
  hgemm<<<dim3(4,64), 256, HGEMM_SMEM>>>(2304, 2, 2, 5, bng, bnb, nullptr, nullptr, nullptr);
  hgemm<<<dim3(2,64), 256, HGEMM_SMEM>>>(1536, 3, 3, 6, b2, nullptr, nullptr, featA, (float*)d_out);
}

// round 17
// speedup vs baseline: 1.0338x; 1.0087x over previous
#include <cuda_runtime.h>
#include <cuda_bf16.h>
#include <cstdint>
#include <math.h>

#define NB 2
#define NN 4096
#define NC 256
#define NH 8
#define NK 32
#define NM (NB*NN)   // 8192

typedef __nv_bfloat16 bf16;

// ---------------- scratch (device globals; no allocation) ----------------
__device__ float g_qs [NM*NC];
__device__ float g_ks [NM*NC];
__device__ float g_v  [NM*NC];
__device__ float g_qd [NM*NC];
__device__ float g_kd [NM*NC];
__device__ int   g_idx[NM*NK];

// bf16 split activations (A operands, row layout [hi | lo | hi], K' = 3K)
__device__ bf16 g_xAnb[(size_t)NM*768];    // K=256 -> 768
__device__ bf16 g_xBb [(size_t)NM*768];
__device__ bf16 g_f1b [(size_t)NM*2304];   // concat K=768 -> 2304
__device__ bf16 g_y1b [(size_t)NM*1536];   // K=512 -> 1536
// bf16 split weights (B operands, row layout [hi | hi | lo], [O][3K])
__device__ bf16 g_wAb[(size_t)512*768];    // wq|wqd rows
__device__ bf16 g_wBb[(size_t)768*768];    // wk|wv|wkd rows
__device__ bf16 g_w1b[(size_t)512*2304];
__device__ bf16 g_w2b[(size_t)256*1536];

__device__ __forceinline__ void bsplit(float v, bf16& h, bf16& l) {
  h = __float2bfloat16(v);
  l = __float2bfloat16(v - __bfloat162float(h));
}

// ---------------- weight prep: bf16 split, [O][3K] ----------------
__global__ void prep_weights(const float* wq, const float* wk, const float* wv,
                             const float* wqd, const float* wkd,
                             const float* w1, const float* w2) {
  int i = blockIdx.x * blockDim.x + threadIdx.x;
  const int S5 = 5 * NC * NC;          // 327680
  const int S1 = S5 + 3*NC*2*NC;       // 720896
  const int TOT = S1 + 2*NC*NC;        // 851968
  if (i >= TOT) return;
  bf16 h, l;
  if (i < S5) {
    int r = i / (NC*NC);
    int t = i - r*(NC*NC);
    const float* src = (r==0)?wq:(r==1)?wk:(r==2)?wv:(r==3)?wqd:wkd;
    int o = t / NC, k = t - o*NC;
    bsplit(src[t], h, l);
    bf16* dst; int row;
    if (r == 0)      { dst = g_wAb; row = o; }
    else if (r == 3) { dst = g_wAb; row = NC + o; }
    else if (r == 1) { dst = g_wBb; row = o; }
    else if (r == 2) { dst = g_wBb; row = NC + o; }
    else             { dst = g_wBb; row = 2*NC + o; }
    size_t base = (size_t)row * 768;
    dst[base + k] = h; dst[base + 256 + k] = h; dst[base + 512 + k] = l;
  } else if (i < S1) {
    int t = i - S5; int o = t / 768, k = t - o*768;   // w1 [512][768]
    bsplit(w1[t], h, l);
    size_t base = (size_t)o * 2304;
    g_w1b[base + k] = h; g_w1b[base + 768 + k] = h; g_w1b[base + 1536 + k] = l;
  } else {
    int t = i - S1; int o = t / 512, k = t - o*512;   // w2 [256][512]
    bsplit(w2[t], h, l);
    size_t base = (size_t)o * 1536;
    g_w2b[base + k] = h; g_w2b[base + 512 + k] = h; g_w2b[base + 1024 + k] = l;
  }
}

// ---------------- featB (B,C,N) -> xBb (B,N,3C) bf16 split ----------------
__global__ void transpose_feat(const float* f) {
  __shared__ float t[32][33];
  int b = blockIdx.z;
  int n0 = blockIdx.x*32, c0 = blockIdx.y*32;
  int tx = threadIdx.x, ty = threadIdx.y;
  #pragma unroll
  for (int i = ty; i < 32; i += 8)
    t[i][tx] = f[((size_t)b*NC + c0+i)*NN + n0 + tx];
  __syncthreads();
  #pragma unroll
  for (int i = ty; i < 32; i += 8) {
    bf16 h, l; bsplit(t[tx][i], h, l);
    size_t base = ((size_t)b*NN + n0+i)*768 + c0 + tx;
    g_xBb[base] = h; g_xBb[base + 256] = l; g_xBb[base + 512] = h;
  }
}

// ---------------- fused transpose + LayerNorm: featA -> xAnb + f1b ----------------
__global__ void ln_input(const float* fA, const float* w, const float* bia) {
  __shared__ float t[32][NC+1];
  int b = blockIdx.y;
  int n0 = blockIdx.x*32;
  int tx = threadIdx.x, ty = threadIdx.y;
  for (int c = ty; c < NC; c += 8)
    t[tx][c] = fA[((size_t)b*NC + c)*NN + n0 + tx];
  __syncthreads();
  int warp = ty, lane = tx;
  #pragma unroll
  for (int r = 0; r < 4; r++) {
    int nl = warp*4 + r;
    float s = 0.f, sq = 0.f;
    #pragma unroll
    for (int i = 0; i < 8; i++) { float v = t[nl][lane + 32*i]; s += v; sq += v*v; }
    #pragma unroll
    for (int off = 16; off; off >>= 1) {
      s  += __shfl_xor_sync(0xffffffffu, s, off);
      sq += __shfl_xor_sync(0xffffffffu, sq, off);
    }
    float mean = s * (1.f/NC);
    float var  = sq * (1.f/NC) - mean*mean;
    float rs   = rsqrtf(var + 1e-5f);
    size_t m = (size_t)b*NN + n0 + nl;
    size_t o7 = m*768, oF = m*2304;
    #pragma unroll
    for (int i = 0; i < 8; i++) {
      int c = lane + 32*i;
      float v = (t[nl][c] - mean) * rs * w[c] + bia[c];
      bf16 h, l; bsplit(v, h, l);
      g_xAnb[o7 + c] = h; g_xAnb[o7 + 256 + c] = l; g_xAnb[o7 + 512 + c] = h;
      g_f1b[oF + c] = h;  g_f1b[oF + 768 + c] = l;  g_f1b[oF + 1536 + c] = h;
    }
  }
}

// ---------------- KNN v4: 16 queries/block (512 thr), sorted-insert top-32 ----------------
__device__ __forceinline__ unsigned long long warp_sort32(unsigned long long key, int lane) {
  #pragma unroll
  for (int k = 2; k <= 32; k <<= 1) {
    #pragma unroll
    for (int j = k >> 1; j > 0; j >>= 1) {
      unsigned long long o = __shfl_xor_sync(0xffffffffu, key, j);
      bool up = ((lane & k) == 0);
      bool takeMin = (((lane & j) == 0) == up);
      unsigned long long mn = (key < o) ? key : o;
      unsigned long long mx = (key < o) ? o : key;
      key = takeMin ? mn : mx;
    }
  }
  return key;
}

__global__ __launch_bounds__(512) void knn_kernel(const float* xyzA, const float* xyzB) {
  __shared__ float sx[NN], sy[NN], sz[NN];
  int b = blockIdx.x >> 8;             // 256 blocks per batch (16 queries each)
  int tid = threadIdx.x;
  int lane = tid & 31, warp = tid >> 5;
  int q = blockIdx.x * 16 + warp;

  const float* Bp = xyzB + (size_t)b*NN*3;
  for (int i = tid; i < NN*3; i += 512) {
    float v = Bp[i];
    int p = i / 3, c = i - p*3;
    if (c == 0) sx[p] = v; else if (c == 1) sy[p] = v; else sz[p] = v;
  }
  __syncthreads();

  const float* Ap = xyzA + (size_t)q*3;
  float ax = Ap[0], ay = Ap[1], az = Ap[2];
  float sA = ax*ax + ay*ay + az*az;

  auto mkkey = [&](int j) -> unsigned long long {
    float bx = sx[j], by = sy[j], bz = sz[j];
    float d2 = sA + (bx*bx + by*by + bz*bz) - 2.f*(ax*bx + ay*by + az*bz);
    unsigned u = __float_as_uint(d2);
    u = (u & 0x80000000u) ? ~u : (u | 0x80000000u);
    return ((unsigned long long)u << 32) | (unsigned)j;
  };

  unsigned long long topk = warp_sort32(mkkey(lane), lane);
  unsigned long long thr = __shfl_sync(0xffffffffu, topk, 31);

  for (int it = 1; it < NN/32; it++) {
    unsigned long long ck = mkkey(it*32 + lane);
    unsigned ball = __ballot_sync(0xffffffffu, ck < thr);
    while (ball) {
      int src = __ffs(ball) - 1;
      ball &= ball - 1;
      unsigned long long cand = __shfl_sync(0xffffffffu, ck, src);
      if (cand >= thr) continue;
      unsigned long long prev = __shfl_up_sync(0xffffffffu, topk, 1);
      bool shift = (topk > cand);
      unsigned long long nv = (lane > 0 && prev > cand) ? prev : cand;
      topk = shift ? nv : topk;
      thr = __shfl_sync(0xffffffffu, topk, 31);
    }
  }
  g_idx[(size_t)q*NK + lane] = (int)(unsigned)(topk & 0xffffffffull);
}

// ---------------- dual-path attention (gather + softmax + ctx + LN) ----------------
__global__ __launch_bounds__(256) void attn_kernel(const float* lsw, const float* lsb,
                                                   const float* ldw, const float* ldb) {
  int q = blockIdx.x;
  int b = q >> 12;
  int tid = threadIdx.x, h = tid >> 5, lane = tid & 31;
  __shared__ int sidx[NK];
  __shared__ float sS[NH][NK];
  __shared__ float sD[NH][NK];
  __shared__ float4 rbuf[NH];
  if (tid < NK) sidx[tid] = g_idx[(size_t)q*NK + tid];
  __syncthreads();
  float qs = g_qs[(size_t)q*NC + tid];
  float qd = g_qd[(size_t)q*NC + tid];
  size_t bb = (size_t)b*NN*NC;
  #pragma unroll
  for (int k0 = 0; k0 < NK; k0 += 4) {
    float a[4], c[4];
    #pragma unroll
    for (int u = 0; u < 4; u++) {
      size_t base = bb + (size_t)sidx[k0+u]*NC + tid;
      a[u] = g_ks[base];
      c[u] = g_kd[base];
    }
    #pragma unroll
    for (int u = 0; u < 4; u++) {
      float ps = qs * a[u];
      float df = qd - c[u];
      float pd = df * df;
      #pragma unroll
      for (int off = 16; off; off >>= 1) {
        ps += __shfl_down_sync(0xffffffffu, ps, off);
        pd += __shfl_down_sync(0xffffffffu, pd, off);
      }
      if (lane == 0) {
        sS[h][k0+u] = ps * 0.17677669529663687f;
        sD[h][k0+u] = sqrtf(pd);
      }
    }
  }
  __syncwarp();
  {
    float sv = sS[h][lane];
    float mx = sv;
    #pragma unroll
    for (int off = 16; off; off >>= 1) mx = fmaxf(mx, __shfl_xor_sync(0xffffffffu, mx, off));
    float e = expf(sv - mx);
    float s = e;
    #pragma unroll
    for (int off = 16; off; off >>= 1) s += __shfl_xor_sync(0xffffffffu, s, off);
    sS[h][lane] = e / s;

    float dv = sD[h][lane];
    float mx2 = dv;
    #pragma unroll
    for (int off = 16; off; off >>= 1) mx2 = fmaxf(mx2, __shfl_xor_sync(0xffffffffu, mx2, off));
    float e2 = expf(dv - mx2);
    float s2 = e2;
    #pragma unroll
    for (int off = 16; off; off >>= 1) s2 += __shfl_xor_sync(0xffffffffu, s2, off);
    sD[h][lane] = e2 / s2;
  }
  __syncwarp();
  float accs = 0.f, accd = 0.f;
  #pragma unroll
  for (int k0 = 0; k0 < NK; k0 += 4) {
    float vv[4];
    #pragma unroll
    for (int u = 0; u < 4; u++) vv[u] = g_v[bb + (size_t)sidx[k0+u]*NC + tid];
    #pragma unroll
    for (int u = 0; u < 4; u++) { accs += sS[h][k0+u]*vv[u]; accd += sD[h][k0+u]*vv[u]; }
  }
  float4 red = make_float4(accs, accs*accs, accd, accd*accd);
  #pragma unroll
  for (int off = 16; off; off >>= 1) {
    red.x += __shfl_xor_sync(0xffffffffu, red.x, off);
    red.y += __shfl_xor_sync(0xffffffffu, red.y, off);
    red.z += __shfl_xor_sync(0xffffffffu, red.z, off);
    red.w += __shfl_xor_sync(0xffffffffu, red.w, off);
  }
  if (lane == 0) rbuf[h] = red;
  __syncthreads();
  float4 tot = rbuf[0];
  #pragma unroll
  for (int w = 1; w < 8; w++) { float4 r = rbuf[w]; tot.x += r.x; tot.y += r.y; tot.z += r.z; tot.w += r.w; }
  float ms = tot.x * (1.f/NC), vs = tot.y * (1.f/NC) - ms*ms;
  float md = tot.z * (1.f/NC), vd = tot.w * (1.f/NC) - md*md;
  float ys = (accs - ms) * rsqrtf(vs + 1e-5f) * lsw[tid] + lsb[tid];
  float yd = (accd - md) * rsqrtf(vd + 1e-5f) * ldw[tid] + ldb[tid];
  size_t oF = (size_t)q*2304;
  bf16 hh, ll;
  bsplit(ys, hh, ll);   // ctx_s occupies concat cols [256,512)
  g_f1b[oF + 256 + tid] = hh; g_f1b[oF + 1024 + tid] = ll; g_f1b[oF + 1792 + tid] = hh;
  bsplit(yd, hh, ll);   // ctx_d occupies concat cols [512,768)
  g_f1b[oF + 512 + tid] = hh; g_f1b[oF + 1280 + tid] = ll; g_f1b[oF + 2048 + tid] = hh;
}

// ================= bf16 tensor-core GEMM via mma.sync + cp.async (sm_100 baseline ISA) =================
__device__ __forceinline__ uint32_t smem_u32(const void* p) {
  uint32_t a;
  asm("{ .reg .u64 t; cvta.to.shared.u64 t, %1; cvt.u32.u64 %0, t; }" : "=r"(a) : "l"(p));
  return a;
}
__device__ __forceinline__ void ldsm4(uint32_t* r, uint32_t addr) {
  asm volatile("ldmatrix.sync.aligned.m8n8.x4.shared.b16 {%0,%1,%2,%3}, [%4];"
    : "=r"(r[0]), "=r"(r[1]), "=r"(r[2]), "=r"(r[3]) : "r"(addr));
}
__device__ __forceinline__ void mma16816(float* d, const uint32_t* a, const uint32_t* b) {
  asm volatile("mma.sync.aligned.m16n8k16.row.col.f32.bf16.bf16.f32 "
    "{%0,%1,%2,%3}, {%4,%5,%6,%7}, {%8,%9}, {%0,%1,%2,%3};"
    : "+f"(d[0]), "+f"(d[1]), "+f"(d[2]), "+f"(d[3])
    : "r"(a[0]), "r"(a[1]), "r"(a[2]), "r"(a[3]), "r"(b[0]), "r"(b[1]));
}
__device__ __forceinline__ void cpasync16(uint32_t dst, const void* src) {
  asm volatile("cp.async.cg.shared.global [%0], [%1], 16;" :: "r"(dst), "l"(src) : "memory");
}

__device__ __forceinline__ const bf16* selAb(int s) {
  switch (s) { case 0: return g_xAnb; case 1: return g_xBb; case 2: return g_f1b; }
  return g_y1b;
}
__device__ __forceinline__ const bf16* selWb(int s) {
  switch (s) { case 0: return g_wAb; case 1: return g_wBb; case 2: return g_w1b; }
  return g_w2b;
}

#define KCH 64      // K-chunk width (bf16)
#define SROW 72     // smem row stride in bf16 (144 B) — conflict-free LDSM phases
#define STAGE (128*SROW)
#define HGEMM_SMEM (4*STAGE*2)   // 2 stages x (A+B) x 128xSROW bf16 = 73728 B
#define TPAD 132    // fp32 transpose-staging row stride (128x132x4 = 67584 B <= HGEMM_SMEM)

extern __shared__ __align__(16) bf16 hg_dyn[];

__global__ __launch_bounds__(256, 2) void hgemm(int Kp, int aSel, int wSel, int outSel,
                                                const float* e1, const float* e2, const float* e3,
                                                const float* fA, float* outp) {
  const int tid = threadIdx.x;
  const int warp = tid >> 5, lane = tid & 31;
  const int wm = (warp & 1) * 64;    // warp M offset (2 warps in M)
  const int wn = (warp >> 1) * 32;   // warp N offset (4 warps in N)
  const int m0 = blockIdx.y * 128;
  const int n0 = blockIdx.x * 128;
  const bf16* Ab = selAb(aSel);
  const bf16* Wb = selWb(wSel);
  const uint32_t sA = smem_u32(hg_dyn);            // stages 0,1 of A
  const uint32_t sB = sA + 2*STAGE*2;              // stages 0,1 of B

  float acc[4][4][4];
  #pragma unroll
  for (int i = 0; i < 4; i++)
    #pragma unroll
    for (int j = 0; j < 4; j++)
      #pragma unroll
      for (int c = 0; c < 4; c++) acc[i][j][c] = 0.f;

  // cp.async load: chunk = 128 rows x 64 bf16 = 1024 x 16B per operand; 4/thread
  const int gRow = tid >> 3;           // rows 0..31 (+32,+64,+96)
  const int gSeg = (tid & 7) * 8;      // bf16 offset within chunk row

  auto cpload = [&](int buf, int ch) {
    #pragma unroll
    for (int i = 0; i < 4; i++) {
      int row = gRow + i*32;
      uint32_t soff = (buf*STAGE + row*SROW + gSeg) * 2;
      cpasync16(sA + soff, Ab + (size_t)(m0 + row)*Kp + ch*KCH + gSeg);
      cpasync16(sB + soff, Wb + (size_t)(n0 + row)*Kp + ch*KCH + gSeg);
    }
    asm volatile("cp.async.commit_group;" ::: "memory");
  };

  // ldmatrix address components
  const int aRowSel = lane & 15;            // m-row within 16
  const int aKSel   = (lane >> 4) * 8;      // k-offset 0/8
  const int bMtx    = lane >> 3;            // 0..3
  const int bRowSel = lane & 7;
  const int bNOff   = (bMtx >> 1) * 8;
  const int bKOff   = (bMtx & 1) * 8;

  const int nCh = Kp / KCH;
  cpload(0, 0);
  for (int ch = 0; ch < nCh; ch++) {
    if (ch + 1 < nCh) {
      cpload((ch + 1) & 1, ch + 1);
      asm volatile("cp.async.wait_group 1;" ::: "memory");
    } else {
      asm volatile("cp.async.wait_group 0;" ::: "memory");
    }
    __syncthreads();
    const uint32_t bufOff = (uint32_t)((ch & 1) * STAGE) * 2;
    #pragma unroll
    for (int ks = 0; ks < KCH/16; ks++) {
      uint32_t af[4][4], bfr[4][2];
      #pragma unroll
      for (int mi = 0; mi < 4; mi++) {
        uint32_t addr = sA + bufOff + ((wm + mi*16 + aRowSel)*SROW + ks*16 + aKSel)*2;
        ldsm4(af[mi], addr);
      }
      #pragma unroll
      for (int p = 0; p < 2; p++) {
        uint32_t r[4];
        uint32_t addr = sB + bufOff + ((wn + p*16 + bNOff + bRowSel)*SROW + ks*16 + bKOff)*2;
        ldsm4(r, addr);
        bfr[2*p][0] = r[0]; bfr[2*p][1] = r[1];
        bfr[2*p+1][0] = r[2]; bfr[2*p+1][1] = r[3];
      }
      #pragma unroll
      for (int mi = 0; mi < 4; mi++)
        #pragma unroll
        for (int ni = 0; ni < 4; ni++)
          mma16816(acc[mi][ni], af[mi], bfr[ni]);
    }
    __syncthreads();   // buffer (ch&1) reusable for cp.async next iteration
  }

  // ---- epilogue ----
  const int t4 = lane & 3, qd = lane >> 2;
  const float BNS = rsqrtf(1.f + 1e-5f);
  if (outSel == 6) {
    // fusion2: +bias into smem [n][m] (conflict-free), then coalesced residual+store
    float* sm = (float*)hg_dyn;
    #pragma unroll
    for (int mi = 0; mi < 4; mi++) {
      #pragma unroll
      for (int half = 0; half < 2; half++) {
        int ml = wm + mi*16 + qd + half*8;
        #pragma unroll
        for (int ni = 0; ni < 4; ni++) {
          int nl = wn + ni*8 + t4*2;
          sm[nl*TPAD + ml]     = acc[mi][ni][half*2 + 0] + e1[n0 + nl];
          sm[(nl+1)*TPAD + ml] = acc[mi][ni][half*2 + 1] + e1[n0 + nl + 1];
        }
      }
    }
    __syncthreads();
    int bb2 = m0 >> 12, mt = m0 & 4095;
    #pragma unroll
    for (int f = tid; f < 128*32; f += 256) {
      int rn = f >> 5, c4 = (f & 31) * 4;
      size_t o = ((size_t)bb2*NC + n0 + rn)*NN + mt + c4;
      float4 v = *(float4*)&sm[rn*TPAD + c4];
      float4 a = *(const float4*)&fA[o];
      v.x += a.x; v.y += a.y; v.z += a.z; v.w += a.w;
      *(float4*)&outp[o] = v;
    }
    return;
  }
  #pragma unroll
  for (int mi = 0; mi < 4; mi++) {
    #pragma unroll
    for (int half = 0; half < 2; half++) {
      int m = m0 + wm + mi*16 + qd + half*8;
      #pragma unroll
      for (int ni = 0; ni < 4; ni++) {
        int n = n0 + wn + ni*8 + t4*2;
        float v0 = acc[mi][ni][half*2 + 0];
        float v1 = acc[mi][ni][half*2 + 1];
        if (outSel == 5) {               // fusion1: BN + ReLU -> bf16 split y1b
          float y0 = fmaxf(v0 * BNS * e1[n]   + e2[n],   0.f);
          float y1 = fmaxf(v1 * BNS * e1[n+1] + e2[n+1], 0.f);
          bf16 h0, l0, h1, l1; bsplit(y0, h0, l0); bsplit(y1, h1, l1);
          size_t base = (size_t)m*1536 + n;
          g_y1b[base]        = h0; g_y1b[base+1]      = h1;
          g_y1b[base + 512]  = l0; g_y1b[base+513]    = l1;
          g_y1b[base + 1024] = h0; g_y1b[base+1025]   = h1;
        } else {                         // projections: +bias -> fp32 segment
          float* dst; const float* bias;
          if (outSel == 10) { dst = (n < 256) ? g_qs : g_qd; bias = (n < 256) ? e1 : e2; }
          else { int sg = n >> 8; dst = (sg == 0) ? g_ks : (sg == 1) ? g_v : g_kd;
                 bias = (sg == 0) ? e1 : (sg == 1) ? e2 : e3; }
          int lc = n & 255;
          float2 o2 = make_float2(v0 + bias[lc], v1 + bias[lc+1]);
          *(float2*)(dst + (size_t)m*NC + lc) = o2;
        }
      }
    }
  }
}

// ---------------- launch ----------------
extern "C" void kernel_launch(void* const* d_in, const int* in_sizes, int n_in,
                              void* d_out, int out_size) {
  const float* xyzA   = (const float*)d_in[0];
  const float* xyzB   = (const float*)d_in[1];
  const float* featA  = (const float*)d_in[2];
  const float* featB  = (const float*)d_in[3];
  const float* ln_in_w = (const float*)d_in[4];
  const float* ln_in_b = (const float*)d_in[5];
  const float* wq  = (const float*)d_in[6];  const float* bq  = (const float*)d_in[7];
  const float* wk  = (const float*)d_in[8];  const float* bk  = (const float*)d_in[9];
  const float* wv  = (const float*)d_in[10]; const float* bv  = (const float*)d_in[11];
  const float* wqd = (const float*)d_in[12]; const float* bqd = (const float*)d_in[13];
  const float* wkd = (const float*)d_in[14]; const float* bkd = (const float*)d_in[15];
  const float* lsw = (const float*)d_in[16]; const float* lsb = (const float*)d_in[17];
  const float* ldw = (const float*)d_in[18]; const float* ldb = (const float*)d_in[19];
  const float* w1  = (const float*)d_in[20];
  const float* bng = (const float*)d_in[21]; const float* bnb = (const float*)d_in[22];
  const float* w2  = (const float*)d_in[23]; const float* b2  = (const float*)d_in[24];

  // side streams + fork/join events (created once; identical captured work per call)
  static cudaStream_t s1 = nullptr, s2 = nullptr, s3 = nullptr;
  static cudaEvent_t evFork = nullptr, evPrep = nullptr, evKnn = nullptr,
                     evP1 = nullptr, evP2 = nullptr;
  if (s1 == nullptr) {
    cudaStreamCreateWithFlags(&s1, cudaStreamNonBlocking);
    cudaStreamCreateWithFlags(&s2, cudaStreamNonBlocking);
    cudaStreamCreateWithFlags(&s3, cudaStreamNonBlocking);
    cudaEventCreateWithFlags(&evFork, cudaEventDisableTiming);
    cudaEventCreateWithFlags(&evPrep, cudaEventDisableTiming);
    cudaEventCreateWithFlags(&evKnn,  cudaEventDisableTiming);
    cudaEventCreateWithFlags(&evP1,   cudaEventDisableTiming);
    cudaEventCreateWithFlags(&evP2,   cudaEventDisableTiming);
  }

  cudaFuncSetAttribute(hgemm, cudaFuncAttributeMaxDynamicSharedMemorySize, HGEMM_SMEM);

  // ---- fork: 4 independent front-end branches ----
  cudaEventRecord(evFork, 0);
  cudaStreamWaitEvent(s1, evFork, 0);
  cudaStreamWaitEvent(s2, evFork, 0);
  cudaStreamWaitEvent(s3, evFork, 0);

  // s1: knn (ALU-bound, long) — overlaps everything up to attn
  knn_kernel<<<NM/16, 512, 0, s1>>>(xyzA, xyzB);
  cudaEventRecord(evKnn, s1);

  // main: weight prep (needed by all GEMMs)
  prep_weights<<<(851968 + 255)/256, 256>>>(wq, wk, wv, wqd, wkd, w1, w2);
  cudaEventRecord(evPrep, 0);

  // s2: ln_input -> proj1 (q_s|q_d)
  ln_input<<<dim3(128,2), dim3(32,8), 0, s2>>>(featA, ln_in_w, ln_in_b);
  cudaStreamWaitEvent(s2, evPrep, 0);
  hgemm<<<dim3(4,64), 256, HGEMM_SMEM, s2>>>(768, 0, 0, 10, bq, bqd, nullptr, nullptr, nullptr);
  cudaEventRecord(evP1, s2);

  // s3: transpose_feat -> proj2 (k_s|v|k_d)
  transpose_feat<<<dim3(128,8,2), dim3(32,8), 0, s3>>>(featB);
  cudaStreamWaitEvent(s3, evPrep, 0);
  hgemm<<<dim3(6,64), 256, HGEMM_SMEM, s3>>>(768, 1, 1, 11, bk, bv, bkd, nullptr, nullptr);
  cudaEventRecord(evP2, s3);

  // ---- join: attention needs knn indices + both projections ----
  cudaStreamWaitEvent(0, evKnn, 0);
  cudaStreamWaitEvent(0, evP1, 0);
  cudaStreamWaitEvent(0, evP2, 0);
  attn_kernel<<<NM, 256>>>(lsw, lsb, ldw, ldb);

  // fusion MLP: concat -> w1 (BN+ReLU) -> w2 (+b2 + residual, smem-staged transposed store)
  hgemm<<<dim3(4,64), 256, HGEMM_SMEM>>>(2304, 2, 2, 5, bng, bnb, nullptr, nullptr, nullptr);
  hgemm<<<dim3(2,64), 256, HGEMM_SMEM>>>(1536, 3, 3, 6, b2, nullptr, nullptr, featA, (float*)d_out);
}